// round 6
// baseline (speedup 1.0000x reference)
#include <cuda_runtime.h>
#include <mma.h>
#include <cstdint>

using namespace nvcuda;

// Problem constants
#define B_      128
#define CIN     128
#define LEGO_   128
#define OUTC    512
#define HW      1024
#define W_IMG   32
#define KTOT    1152          // 128 ic * 9 taps
#define KCHUNK  32
#define NCHUNKS 36            // 1152 / 32
#define NTILE   128           // pixels per CTA
#define LDA     36            // A smem leading dim (K + pad), mult of 4
#define LDB     36            // B smem leading dim (K + pad), col-major
#define LDF     132           // feat smem leading dim (N + pad)

// dynamic smem: max(stage = 128*36 + 36*128, feat = 128*132) floats
#define DSM_BYTES (128 * LDF * 4)   // 67584

__device__ int   g_sel[OUTC];
__device__ float g_scale[OUTC];

__device__ __forceinline__ uint32_t f2tf32(float f) {
    uint32_t u;
    asm("cvt.rna.tf32.f32 %0, %1;" : "=r"(u) : "f"(f));
    return u;
}

// ---------------------------------------------------------------------------
// Kernel 1: forward select map. sel[o] = argmax_l comb[0,o,l]; scale[o].
// ---------------------------------------------------------------------------
__global__ void select_kernel(const float* __restrict__ coeff,
                              const float* __restrict__ comb) {
    int o = threadIdx.x;
    const float* row = comb + o * LEGO_;
    float m = row[0];
    int mi = 0;
    #pragma unroll 4
    for (int l = 1; l < LEGO_; l++) {
        float v = row[l];
        if (v > m) { m = v; mi = l; }
    }
    g_sel[o]   = mi;
    g_scale[o] = coeff[o * LEGO_ + mi];
}

// ---------------------------------------------------------------------------
// Kernel 2: tf32 wmma implicit-GEMM conv + fused scatter.
// grid = (8 pixel tiles, 128 batches), 256 threads (8 warps).
// Warp w computes LEGO rows [16w, 16w+16) x all 128 pixels.
// ---------------------------------------------------------------------------
__global__ __launch_bounds__(256, 2)
void conv_wmma_kernel(const float* __restrict__ x,
                      const int*   __restrict__ label,
                      const float* __restrict__ ff,
                      float*       __restrict__ out) {
    extern __shared__ float dsm[];
    float* sA = dsm;                  // [128][LDA] row-major: (m,k) at m*LDA+k
    float* sB = dsm + 128 * LDA;      // col-major: (k,n) at k + n*LDB

    const int tid  = threadIdx.x;
    const int wid  = tid >> 5;
    const int lid  = tid & 31;
    const int tile = blockIdx.x;      // 0..7
    const int b    = blockIdx.y;      // 0..127
    const int pix0 = tile * NTILE;

    const int lab = label[b];
    const float* xb = x  + (size_t)b   * CIN   * HW;
    const float* wb = ff + (size_t)lab * LEGO_ * KTOT;

    wmma::fragment<wmma::accumulator, 16, 16, 8, float> acc[8];
    #pragma unroll
    for (int nt = 0; nt < 8; nt++) wmma::fill_fragment(acc[nt], 0.0f);

    // fill-thread coordinates
    const int am   = tid >> 1;        // A row 0..127
    const int ah   = tid & 1;         // A half (16 k each)
    const int bn   = tid & 127;       // B pixel 0..127
    const int bh   = tid >> 7;        // B half (16 k each)
    const int br   = (pix0 + bn) >> 5;   // image row of pixel bn
    const int bc   = bn & 31;            // image col

    for (int chunk = 0; chunk < NCHUNKS; chunk++) {
        const int k0 = chunk * KCHUNK;
        __syncthreads();              // previous chunk's compute done

        // ---- A fill: 16 contiguous weights per thread, tf32-rounded ----
        {
            const float* src = wb + (size_t)am * KTOT + k0 + ah * 16;
            uint32_t* dst = reinterpret_cast<uint32_t*>(sA + am * LDA + ah * 16);
            #pragma unroll
            for (int j = 0; j < 4; j++) {
                float4 v = *reinterpret_cast<const float4*>(src + j * 4);
                uint4 t4;
                t4.x = f2tf32(v.x); t4.y = f2tf32(v.y);
                t4.z = f2tf32(v.z); t4.w = f2tf32(v.w);
                *reinterpret_cast<uint4*>(dst + j * 4) = t4;
            }
        }
        // ---- B fill: im2col gather, 16 k-values for pixel bn ----
        {
            uint32_t* colp = reinterpret_cast<uint32_t*>(sB + bn * LDB);
            #pragma unroll
            for (int kc = 0; kc < 16; kc++) {
                const int krel = bh * 16 + kc;
                const int kg   = k0 + krel;
                const int ic   = kg / 9;
                const int tap  = kg - ic * 9;
                const int kh   = tap / 3;
                const int kw   = tap - kh * 3;
                const int rr   = br + kh - 1;
                const int cc   = bc + kw - 1;
                const bool ok  = (rr >= 0) & (rr < 32) & (cc >= 0) & (cc < 32);
                float v = ok ? __ldg(xb + ic * HW + rr * W_IMG + cc) : 0.0f;
                colp[krel] = f2tf32(v);
            }
        }
        __syncthreads();

        // ---- compute: 4 k-steps x 8 n-tiles ----
        #pragma unroll
        for (int ks = 0; ks < 4; ks++) {
            wmma::fragment<wmma::matrix_a, 16, 16, 8,
                           wmma::precision::tf32, wmma::row_major> af;
            wmma::load_matrix_sync(af, sA + (wid * 16) * LDA + ks * 8, LDA);
            #pragma unroll
            for (int nt = 0; nt < 8; nt++) {
                wmma::fragment<wmma::matrix_b, 16, 16, 8,
                               wmma::precision::tf32, wmma::col_major> bf;
                wmma::load_matrix_sync(bf, sB + ks * 8 + (nt * 16) * LDB, LDB);
                wmma::mma_sync(acc[nt], af, bf, acc[nt]);
            }
        }
    }

    __syncthreads();                  // stage buffer dead; reuse as feat
    float* feat = dsm;                // [128][LDF]
    #pragma unroll
    for (int nt = 0; nt < 8; nt++)
        wmma::store_matrix_sync(feat + (wid * 16) * LDF + nt * 16,
                                acc[nt], LDF, wmma::mem_row_major);
    __syncthreads();

    // ---- coalesced scatter: out[b, o, pix0 + lid*4 .. +3] ----
    float* outb = out + (size_t)b * OUTC * HW + pix0;
    for (int o = wid; o < OUTC; o += 8) {
        const int   sl = g_sel[o];
        const float sc = g_scale[o];
        float4 v = *reinterpret_cast<const float4*>(&feat[sl * LDF + lid * 4]);
        v.x *= sc; v.y *= sc; v.z *= sc; v.w *= sc;
        *reinterpret_cast<float4*>(outb + (size_t)o * HW + lid * 4) = v;
    }
}

// ---------------------------------------------------------------------------
extern "C" void kernel_launch(void* const* d_in, const int* in_sizes, int n_in,
                              void* d_out, int out_size) {
    const float* x     = (const float*)d_in[0];
    const int*   label = (const int*)  d_in[1];
    const float* ff    = (const float*)d_in[2];
    const float* coeff = (const float*)d_in[3];
    const float* comb  = (const float*)d_in[4];
    float*       out   = (float*)d_out;

    static bool attr_set = false;
    if (!attr_set) {
        cudaFuncSetAttribute(conv_wmma_kernel,
                             cudaFuncAttributeMaxDynamicSharedMemorySize,
                             DSM_BYTES);
        attr_set = true;
    }

    select_kernel<<<1, OUTC>>>(coeff, comb);

    dim3 grid(HW / NTILE, B_);   // (8, 128)
    conv_wmma_kernel<<<grid, 256, DSM_BYTES>>>(x, label, ff, out);
}

// round 7
// speedup vs baseline: 2.8641x; 2.8641x over previous
#include <cuda_runtime.h>
#include <cuda_fp16.h>
#include <mma.h>
#include <cstdint>

using namespace nvcuda;

// Problem constants
#define B_      128
#define CIN     128
#define LEGO_   128
#define OUTC    512
#define HW      1024
#define W_IMG   32
#define KTOT    1152          // 128 ic * 9 taps
#define KCHUNK  32
#define NCHUNKS 36
#define NTILE   128           // pixels per CTA
#define LDA     40            // A smem ld (halfs), mult of 8
#define LDB     40            // B smem ld (halfs), col-major
#define LDF     132           // feat smem ld (floats)

#define STAGE_HALFS (128 * LDA + 128 * LDB)    // 10240 halfs = 20480 B
#define DSM_BYTES   (128 * LDF * 4)            // 67584 B  (>= 2 stages = 40960)

__device__ int   g_sel[OUTC];
__device__ float g_scale[OUTC];

// ---------------------------------------------------------------------------
// Kernel 1: forward select map. sel[o] = argmax_l comb[0,o,l]; scale[o].
// ---------------------------------------------------------------------------
__global__ void select_kernel(const float* __restrict__ coeff,
                              const float* __restrict__ comb) {
    int o = threadIdx.x;
    const float* row = comb + o * LEGO_;
    float m = row[0];
    int mi = 0;
    #pragma unroll 4
    for (int l = 1; l < LEGO_; l++) {
        float v = row[l];
        if (v > m) { m = v; mi = l; }
    }
    g_sel[o]   = mi;
    g_scale[o] = coeff[o * LEGO_ + mi];
}

// ---------------------------------------------------------------------------
// Kernel 2: fp16 wmma implicit-GEMM conv, 2-stage pipelined, fused scatter.
// grid = (8 pixel tiles, 128 batches), 256 threads (8 warps, 4x2 tiling).
// Warp (wid&3, wid>>2) computes LEGO rows [32*(wid&3), +32) x pixels
// [64*(wid>>2), +64).
// ---------------------------------------------------------------------------
__global__ __launch_bounds__(256, 2)
void conv_wmma_kernel(const float* __restrict__ x,
                      const int*   __restrict__ label,
                      const float* __restrict__ ff,
                      float*       __restrict__ out) {
    extern __shared__ char dsm[];
    __shared__ int         s_off[KTOT];
    __shared__ signed char s_dh[KTOT];
    __shared__ signed char s_dw[KTOT];

    const int tid  = threadIdx.x;
    const int wid  = tid >> 5;
    const int lid  = tid & 31;
    const int tile = blockIdx.x;      // 0..7
    const int b    = blockIdx.y;      // 0..127
    const int pix0 = tile * NTILE;

    // ---- one-time im2col index tables ----
    for (int k = tid; k < KTOT; k += 256) {
        int ic = k / 9, tap = k - ic * 9;
        int dh = tap / 3, dw = tap - dh * 3;
        s_off[k] = ic * HW + (dh - 1) * W_IMG + (dw - 1);
        s_dh[k]  = (signed char)dh;
        s_dw[k]  = (signed char)dw;
    }

    const int lab = label[b];
    const float* xb = x  + (size_t)b   * CIN   * HW;
    const float* wb = ff + (size_t)lab * LEGO_ * KTOT;

    // fill roles: every thread stages 16 A elems + 16 B elems per chunk
    const int am = tid >> 1, ah = tid & 1;          // A: row, k-half
    const int bn = tid & 127, bh = tid >> 7;        // B: pixel, k-half
    const int pr = (pix0 + bn) >> 5, pc = bn & 31;  // image row/col of pixel
    const float* bbase = xb + pr * W_IMG + pc;

    // warp tile (4x2): 32 M-rows x 64 N-cols
    const int mrow = (wid & 3) * 32;
    const int ncol = (wid >> 2) * 64;

    half* stA[2]; half* stB[2];
    stA[0] = reinterpret_cast<half*>(dsm);
    stB[0] = stA[0] + 128 * LDA;
    stA[1] = stB[0] + 128 * LDB;
    stB[1] = stA[1] + 128 * LDA;

    wmma::fragment<wmma::accumulator, 16, 16, 16, float> acc[2][4];
    #pragma unroll
    for (int mi = 0; mi < 2; mi++)
        #pragma unroll
        for (int ni = 0; ni < 4; ni++) wmma::fill_fragment(acc[mi][ni], 0.0f);

    __syncthreads();   // tables ready

    float4 ra[4];      // staged A (fp32)
    half2  rb[8];      // staged B (fp16 pairs)

    auto load_chunk = [&](int k0) {
        const float* srcA = wb + (size_t)am * KTOT + k0 + ah * 16;
        #pragma unroll
        for (int j = 0; j < 4; j++)
            ra[j] = *reinterpret_cast<const float4*>(srcA + j * 4);
        #pragma unroll
        for (int kc = 0; kc < 16; kc += 2) {
            const int k = k0 + bh * 16 + kc;
            const bool ok0 = ((unsigned)(pr + s_dh[k]     - 1) < 32u) &
                             ((unsigned)(pc + s_dw[k]     - 1) < 32u);
            const bool ok1 = ((unsigned)(pr + s_dh[k + 1] - 1) < 32u) &
                             ((unsigned)(pc + s_dw[k + 1] - 1) < 32u);
            float v0 = ok0 ? __ldg(bbase + s_off[k])     : 0.0f;
            float v1 = ok1 ? __ldg(bbase + s_off[k + 1]) : 0.0f;
            rb[kc >> 1] = __floats2half2_rn(v0, v1);
        }
    };
    auto store_chunk = [&](int s) {
        half* dA = stA[s] + am * LDA + ah * 16;
        #pragma unroll
        for (int j = 0; j < 4; j++) {
            *reinterpret_cast<half2*>(dA + j * 4)     =
                __floats2half2_rn(ra[j].x, ra[j].y);
            *reinterpret_cast<half2*>(dA + j * 4 + 2) =
                __floats2half2_rn(ra[j].z, ra[j].w);
        }
        half* dB = stB[s] + bn * LDB + bh * 16;
        #pragma unroll
        for (int j = 0; j < 8; j++)
            *reinterpret_cast<half2*>(dB + j * 2) = rb[j];
    };

    // prologue: stage chunk 0
    load_chunk(0);
    store_chunk(0);
    __syncthreads();

    for (int chunk = 0; chunk < NCHUNKS; chunk++) {
        const int s = chunk & 1;
        if (chunk + 1 < NCHUNKS) load_chunk((chunk + 1) * KCHUNK);

        // ---- compute on stage s ----
        #pragma unroll
        for (int ks = 0; ks < 2; ks++) {
            wmma::fragment<wmma::matrix_a, 16, 16, 16, half,
                           wmma::row_major> af[2];
            #pragma unroll
            for (int mi = 0; mi < 2; mi++)
                wmma::load_matrix_sync(af[mi],
                    stA[s] + (mrow + mi * 16) * LDA + ks * 16, LDA);
            #pragma unroll
            for (int ni = 0; ni < 4; ni++) {
                wmma::fragment<wmma::matrix_b, 16, 16, 16, half,
                               wmma::col_major> bf;
                wmma::load_matrix_sync(bf,
                    stB[s] + (ncol + ni * 16) * LDB + ks * 16, LDB);
                #pragma unroll
                for (int mi = 0; mi < 2; mi++)
                    wmma::mma_sync(acc[mi][ni], af[mi], bf, acc[mi][ni]);
            }
        }

        if (chunk + 1 < NCHUNKS) store_chunk(s ^ 1);
        __syncthreads();
    }

    // ---- feat staging (reuse stage smem) ----
    float* feat = reinterpret_cast<float*>(dsm);
    #pragma unroll
    for (int mi = 0; mi < 2; mi++)
        #pragma unroll
        for (int ni = 0; ni < 4; ni++)
            wmma::store_matrix_sync(
                feat + (mrow + mi * 16) * LDF + ncol + ni * 16,
                acc[mi][ni], LDF, wmma::mem_row_major);
    __syncthreads();

    // ---- coalesced scatter: out[b, o, pix0 + lid*4 .. +3] ----
    float* outb = out + (size_t)b * OUTC * HW + pix0;
    for (int o = wid; o < OUTC; o += 8) {
        const int   sl = g_sel[o];
        const float sc = g_scale[o];
        float4 v = *reinterpret_cast<const float4*>(&feat[sl * LDF + lid * 4]);
        v.x *= sc; v.y *= sc; v.z *= sc; v.w *= sc;
        *reinterpret_cast<float4*>(outb + (size_t)o * HW + lid * 4) = v;
    }
}

// ---------------------------------------------------------------------------
extern "C" void kernel_launch(void* const* d_in, const int* in_sizes, int n_in,
                              void* d_out, int out_size) {
    const float* x     = (const float*)d_in[0];
    const int*   label = (const int*)  d_in[1];
    const float* ff    = (const float*)d_in[2];
    const float* coeff = (const float*)d_in[3];
    const float* comb  = (const float*)d_in[4];
    float*       out   = (float*)d_out;

    static bool attr_set = false;
    if (!attr_set) {
        cudaFuncSetAttribute(conv_wmma_kernel,
                             cudaFuncAttributeMaxDynamicSharedMemorySize,
                             DSM_BYTES);
        attr_set = true;
    }

    select_kernel<<<1, OUTC>>>(coeff, comb);

    dim3 grid(HW / NTILE, B_);   // (8, 128)
    conv_wmma_kernel<<<grid, 256, DSM_BYTES>>>(x, label, ff, out);
}

// round 8
// speedup vs baseline: 2.9722x; 1.0377x over previous
#include <cuda_runtime.h>
#include <cuda_fp16.h>
#include <mma.h>
#include <cstdint>

using namespace nvcuda;

// Problem constants
#define B_      128
#define CIN     128
#define LEGO_   128
#define OUTC    512
#define HW      1024
#define W_IMG   32
#define NLAB    10
#define NTAPS   9
#define KTOT    1152          // 9 taps * 128 ic   (K reordered: k = tap*128 + ic)
#define KCHUNK  32
#define NCHUNKS 36            // 9 taps * 4 ic-blocks
#define NTILE   128           // pixels per CTA (4 image rows)
#define LDA_K   40            // A smem ld (halfs): 80B rows, 16B-aligned
#define LDB_N   136           // B smem ld (halfs): 272B rows, 16B-aligned
#define LDF     132           // feat smem ld (floats)

#define A_STAGE_BYTES (128 * LDA_K * 2)   // 10240
#define B_STAGE_BYTES (KCHUNK * LDB_N * 2) // 8704
#define DSM_BYTES     (128 * LDF * 4)      // 67584 (covers 2 stages = 37888)

__device__ int   g_sel[OUTC];
__device__ float g_scale[OUTC];
__device__ __half g_wA[NLAB * LEGO_ * NTAPS * CIN];          // [lab][m][tap][ic]
__device__ __half g_xsh[3][B_][CIN][W_IMG][W_IMG];           // [dw][b][ic][r][c]

// ---------------------------------------------------------------------------
// Kernel 1: forward select map.
// ---------------------------------------------------------------------------
__global__ void select_kernel(const float* __restrict__ coeff,
                              const float* __restrict__ comb) {
    int o = threadIdx.x;
    const float* row = comb + o * LEGO_;
    float m = row[0];
    int mi = 0;
    #pragma unroll 4
    for (int l = 1; l < LEGO_; l++) {
        float v = row[l];
        if (v > m) { m = v; mi = l; }
    }
    g_sel[o]   = mi;
    g_scale[o] = coeff[o * LEGO_ + mi];
}

// ---------------------------------------------------------------------------
// Kernel 2: weight transpose+convert: wA[lab][m][tap][ic] = ff[lab][m][ic][tap]
// ---------------------------------------------------------------------------
__global__ void prep_w_kernel(const float* __restrict__ ff) {
    int idx = blockIdx.x * 256 + threadIdx.x;       // over 10*128*9*128
    if (idx >= NLAB * LEGO_ * NTAPS * CIN) return;
    int ic  = idx & 127;
    int tap = (idx >> 7) % NTAPS;
    int m   = (idx / (NTAPS * CIN)) & 127;
    int lab = idx / (LEGO_ * NTAPS * CIN);
    float v = ff[((size_t)(lab * LEGO_ + m) * CIN + ic) * NTAPS + tap];
    g_wA[idx] = __float2half_rn(v);
}

// ---------------------------------------------------------------------------
// Kernel 3: build 3 column-shifted fp16 copies of x.
// xsh[dw][b][ic][r][c] = x[b][ic][r][c+dw-1]  (0 outside)
// One thread per (b, ic, r): reads the 32-float row once, writes 3x32 halfs.
// ---------------------------------------------------------------------------
__global__ void prep_x_kernel(const float* __restrict__ x) {
    int idx = blockIdx.x * 256 + threadIdx.x;       // over 128*128*32
    if (idx >= B_ * CIN * W_IMG) return;
    const float* src = x + (size_t)idx * W_IMG;
    float v[32];
    #pragma unroll
    for (int j = 0; j < 8; j++) {
        float4 f = *reinterpret_cast<const float4*>(src + j * 4);
        v[j * 4] = f.x; v[j * 4 + 1] = f.y; v[j * 4 + 2] = f.z; v[j * 4 + 3] = f.w;
    }
    #pragma unroll
    for (int dw = 0; dw < 3; dw++) {
        __half h[32];
        #pragma unroll
        for (int c = 0; c < 32; c++) {
            int s = c + dw - 1;
            h[c] = __float2half_rn((s >= 0 && s < 32) ? v[s] : 0.0f);
        }
        uint4* dst = reinterpret_cast<uint4*>(
            &g_xsh[dw][0][0][0][0] + (size_t)idx * W_IMG);
        #pragma unroll
        for (int j = 0; j < 4; j++)
            dst[j] = reinterpret_cast<const uint4*>(h)[j];
    }
}

// ---------------------------------------------------------------------------
// Kernel 4: fp16 wmma GEMM conv (tap-major K), vectorized fills, 2-stage
// pipeline, fused scatter.  grid = (8 tiles, 128 batches), 256 threads.
// ---------------------------------------------------------------------------
__global__ __launch_bounds__(256, 2)
void conv_wmma_kernel(const int* __restrict__ label,
                      float*     __restrict__ out) {
    extern __shared__ char dsm[];

    const int tid  = threadIdx.x;
    const int wid  = tid >> 5;
    const int lid  = tid & 31;
    const int tile = blockIdx.x;      // 0..7
    const int b    = blockIdx.y;      // 0..127
    const int pix0 = tile * NTILE;
    const int lab  = label[b];

    // fill roles
    const int am = tid >> 1, ah = tid & 1;            // A: row m, 16-half half
    const int kc = tid >> 3;                          // B: k-row within chunk
    const int seg = tid & 7;                          // B: 16-half segment
    const int rhat = seg >> 1, colh = (seg & 1) * 16; // image row in tile, col

    // warp tile (4x2): 32 M x 64 N
    const int mrow = (wid & 3) * 32;
    const int ncol = (wid >> 2) * 64;

    half* stA[2]; half* stB[2];
    stA[0] = reinterpret_cast<half*>(dsm);
    stB[0] = reinterpret_cast<half*>(dsm + A_STAGE_BYTES);
    stA[1] = reinterpret_cast<half*>(dsm + A_STAGE_BYTES + B_STAGE_BYTES);
    stB[1] = reinterpret_cast<half*>(dsm + 2 * A_STAGE_BYTES + B_STAGE_BYTES);

    wmma::fragment<wmma::accumulator, 16, 16, 16, float> acc[2][4];
    #pragma unroll
    for (int mi = 0; mi < 2; mi++)
        #pragma unroll
        for (int ni = 0; ni < 4; ni++) wmma::fill_fragment(acc[mi][ni], 0.0f);

    uint4 ra0, ra1, rb0, rb1;

    auto load_chunk = [&](int chunk) {
        const int tap = chunk >> 2;
        const int ic0 = (chunk & 3) * KCHUNK;
        const int dh  = tap / 3;
        const int dw  = tap - dh * 3;
        // A: 32 contiguous halfs for row am
        const half* srcA = &g_wA[(((size_t)lab * LEGO_ + am) * NTAPS + tap) * CIN
                                 + ic0 + ah * 16];
        ra0 = reinterpret_cast<const uint4*>(srcA)[0];
        ra1 = reinterpret_cast<const uint4*>(srcA)[1];
        // B: shifted image row slice for k-row kc
        const int gr = tile * 4 + rhat + dh - 1;
        if ((unsigned)gr < 32u) {
            const half* srcB = &g_xsh[dw][b][ic0 + kc][gr][colh];
            rb0 = reinterpret_cast<const uint4*>(srcB)[0];
            rb1 = reinterpret_cast<const uint4*>(srcB)[1];
        } else {
            rb0 = make_uint4(0, 0, 0, 0);
            rb1 = make_uint4(0, 0, 0, 0);
        }
    };
    auto store_chunk = [&](int s) {
        uint4* dA = reinterpret_cast<uint4*>(stA[s] + am * LDA_K + ah * 16);
        dA[0] = ra0; dA[1] = ra1;
        uint4* dB = reinterpret_cast<uint4*>(stB[s] + kc * LDB_N
                                             + rhat * 32 + colh);
        dB[0] = rb0; dB[1] = rb1;
    };

    load_chunk(0);
    store_chunk(0);
    __syncthreads();

    for (int chunk = 0; chunk < NCHUNKS; chunk++) {
        const int s = chunk & 1;
        if (chunk + 1 < NCHUNKS) load_chunk(chunk + 1);

        #pragma unroll
        for (int ks = 0; ks < 2; ks++) {
            wmma::fragment<wmma::matrix_a, 16, 16, 16, half,
                           wmma::row_major> af[2];
            #pragma unroll
            for (int mi = 0; mi < 2; mi++)
                wmma::load_matrix_sync(af[mi],
                    stA[s] + (mrow + mi * 16) * LDA_K + ks * 16, LDA_K);
            #pragma unroll
            for (int ni = 0; ni < 4; ni++) {
                wmma::fragment<wmma::matrix_b, 16, 16, 16, half,
                               wmma::row_major> bf;
                wmma::load_matrix_sync(bf,
                    stB[s] + (ks * 16) * LDB_N + ncol + ni * 16, LDB_N);
                #pragma unroll
                for (int mi = 0; mi < 2; mi++)
                    wmma::mma_sync(acc[mi][ni], af[mi], bf, acc[mi][ni]);
            }
        }

        if (chunk + 1 < NCHUNKS) store_chunk(s ^ 1);
        __syncthreads();
    }

    // ---- feat staging (reuse stage smem) ----
    float* feat = reinterpret_cast<float*>(dsm);
    #pragma unroll
    for (int mi = 0; mi < 2; mi++)
        #pragma unroll
        for (int ni = 0; ni < 4; ni++)
            wmma::store_matrix_sync(
                feat + (mrow + mi * 16) * LDF + ncol + ni * 16,
                acc[mi][ni], LDF, wmma::mem_row_major);
    __syncthreads();

    // ---- coalesced scatter: out[b, o, pix0 + lid*4 .. +3] ----
    float* outb = out + (size_t)b * OUTC * HW + pix0;
    for (int o = wid; o < OUTC; o += 8) {
        const int   sl = g_sel[o];
        const float sc = g_scale[o];
        float4 v = *reinterpret_cast<const float4*>(&feat[sl * LDF + lid * 4]);
        v.x *= sc; v.y *= sc; v.z *= sc; v.w *= sc;
        *reinterpret_cast<float4*>(outb + (size_t)o * HW + lid * 4) = v;
    }
}

// ---------------------------------------------------------------------------
extern "C" void kernel_launch(void* const* d_in, const int* in_sizes, int n_in,
                              void* d_out, int out_size) {
    const float* x     = (const float*)d_in[0];
    const int*   label = (const int*)  d_in[1];
    const float* ff    = (const float*)d_in[2];
    const float* coeff = (const float*)d_in[3];
    const float* comb  = (const float*)d_in[4];
    float*       out   = (float*)d_out;

    static bool attr_set = false;
    if (!attr_set) {
        cudaFuncSetAttribute(conv_wmma_kernel,
                             cudaFuncAttributeMaxDynamicSharedMemorySize,
                             DSM_BYTES);
        attr_set = true;
    }

    select_kernel<<<1, OUTC>>>(coeff, comb);
    prep_w_kernel<<<(NLAB * LEGO_ * NTAPS * CIN + 255) / 256, 256>>>(ff);
    prep_x_kernel<<<(B_ * CIN * W_IMG + 255) / 256, 256>>>(x);

    dim3 grid(HW / NTILE, B_);   // (8, 128)
    conv_wmma_kernel<<<grid, 256, DSM_BYTES>>>(label, out);
}

// round 9
// speedup vs baseline: 3.4495x; 1.1606x over previous
#include <cuda_runtime.h>
#include <cuda_fp16.h>
#include <mma.h>
#include <cstdint>

using namespace nvcuda;

// Problem constants
#define B_      128
#define CIN     128
#define LEGO_   128
#define OUTC    512
#define HW      1024
#define W_IMG   32
#define NLAB    10
#define NTAPS   9
#define KCHUNK  32
#define NCHUNKS 36            // 9 taps * 4 ic-blocks  (k = tap*128 + ic)
#define NTILE   256           // pixels per CTA (8 image rows)
#define LDA_K   40            // A smem ld (halfs): 80B rows
#define LDB_N   264           // B smem ld (halfs): 528B rows
#define LDF     260           // feat smem ld (floats)

#define A_STAGE_BYTES (128 * LDA_K * 2)     // 10240
#define B_STAGE_BYTES (KCHUNK * LDB_N * 2)  // 16896
#define STAGE_BYTES   (A_STAGE_BYTES + B_STAGE_BYTES)
#define DSM_BYTES     (128 * LDF * 4)       // 133120 (>= 2*STAGE_BYTES=54272)

__device__ int   g_sel[OUTC];
__device__ float g_scale[OUTC];
__device__ __align__(16) __half g_wA[NLAB * LEGO_ * NTAPS * CIN];  // [lab][m][tap][ic]
__device__ __align__(16) __half g_xsh[3][B_][CIN][W_IMG][W_IMG];   // [dw][b][ic][r][c]

__device__ __forceinline__ uint32_t smem_u32(const void* p) {
    uint32_t a;
    asm("{ .reg .u64 t; cvta.to.shared.u64 t, %1; cvt.u32.u64 %0, t; }"
        : "=r"(a) : "l"(p));
    return a;
}
__device__ __forceinline__ void cp16(uint32_t dst, const void* src, int srcsize) {
    asm volatile("cp.async.cg.shared.global [%0], [%1], 16, %2;"
                 :: "r"(dst), "l"(__cvta_generic_to_global(src)), "r"(srcsize)
                 : "memory");
}
#define CP_COMMIT() asm volatile("cp.async.commit_group;" ::: "memory")
#define CP_WAIT0()  asm volatile("cp.async.wait_group 0;" ::: "memory")

// ---------------------------------------------------------------------------
// Kernel 1: forward select map.
// ---------------------------------------------------------------------------
__global__ void select_kernel(const float* __restrict__ coeff,
                              const float* __restrict__ comb) {
    int o = threadIdx.x;
    const float* row = comb + o * LEGO_;
    float m = row[0];
    int mi = 0;
    #pragma unroll 4
    for (int l = 1; l < LEGO_; l++) {
        float v = row[l];
        if (v > m) { m = v; mi = l; }
    }
    g_sel[o]   = mi;
    g_scale[o] = coeff[o * LEGO_ + mi];
}

// ---------------------------------------------------------------------------
// Kernel 2: weight transpose+convert: wA[lab][m][tap][ic] = ff[lab][m][ic][tap]
// ---------------------------------------------------------------------------
__global__ void prep_w_kernel(const float* __restrict__ ff) {
    int idx = blockIdx.x * 256 + threadIdx.x;
    if (idx >= NLAB * LEGO_ * NTAPS * CIN) return;
    int ic  = idx & 127;
    int tap = (idx >> 7) % NTAPS;
    int m   = (idx / (NTAPS * CIN)) & 127;
    int lab = idx / (LEGO_ * NTAPS * CIN);
    float v = ff[((size_t)(lab * LEGO_ + m) * CIN + ic) * NTAPS + tap];
    g_wA[idx] = __float2half_rn(v);
}

// ---------------------------------------------------------------------------
// Kernel 3: 3 column-shifted fp16 copies of x: xsh[dw][b][ic][r][c] =
// x[b][ic][r][c+dw-1] (0 outside).
// ---------------------------------------------------------------------------
__global__ void prep_x_kernel(const float* __restrict__ x) {
    int idx = blockIdx.x * 256 + threadIdx.x;       // over 128*128*32
    if (idx >= B_ * CIN * W_IMG) return;
    const float* src = x + (size_t)idx * W_IMG;
    float v[32];
    #pragma unroll
    for (int j = 0; j < 8; j++) {
        float4 f = *reinterpret_cast<const float4*>(src + j * 4);
        v[j * 4] = f.x; v[j * 4 + 1] = f.y; v[j * 4 + 2] = f.z; v[j * 4 + 3] = f.w;
    }
    #pragma unroll
    for (int dw = 0; dw < 3; dw++) {
        __half h[32];
        #pragma unroll
        for (int c = 0; c < 32; c++) {
            int s = c + dw - 1;
            h[c] = __float2half_rn((s >= 0 && s < 32) ? v[s] : 0.0f);
        }
        uint4* dst = reinterpret_cast<uint4*>(
            &g_xsh[dw][0][0][0][0] + (size_t)idx * W_IMG);
        #pragma unroll
        for (int j = 0; j < 4; j++)
            dst[j] = reinterpret_cast<const uint4*>(h)[j];
    }
}

// ---------------------------------------------------------------------------
// Kernel 4: fp16 wmma GEMM conv, 64x64 warp tiles, cp.async 2-stage pipeline,
// fused scatter.  grid = (4 tiles, 128 batches), 256 threads (2x4 warps).
// ---------------------------------------------------------------------------
__global__ __launch_bounds__(256, 1)
void conv_wmma_kernel(const int* __restrict__ label,
                      float*     __restrict__ out) {
    extern __shared__ char dsm[];

    const int tid  = threadIdx.x;
    const int wid  = tid >> 5;
    const int lid  = tid & 31;
    const int tile = blockIdx.x;      // 0..3
    const int b    = blockIdx.y;      // 0..127
    const int pix0 = tile * NTILE;
    const int lab  = label[b];

    // fill roles
    const int am   = tid >> 1, ah = tid & 1;   // A: row m, 16-half half
    const int bk   = tid >> 3;                 // B: k-row within chunk (0..31)
    const int bs0  = (tid & 7) * 4;            // B: first 8-half segment (of 32)

    // warp tile: 64 M x 64 N  (warps 2 in M x 4 in N)
    const int mrow = (wid & 1) * 64;
    const int ncol = (wid >> 1) * 64;

    const uint32_t stA[2] = { smem_u32(dsm),
                              smem_u32(dsm + STAGE_BYTES) };
    const uint32_t stB[2] = { stA[0] + A_STAGE_BYTES,
                              stA[1] + A_STAGE_BYTES };
    half* stAp[2] = { reinterpret_cast<half*>(dsm),
                      reinterpret_cast<half*>(dsm + STAGE_BYTES) };
    half* stBp[2] = { reinterpret_cast<half*>(dsm + A_STAGE_BYTES),
                      reinterpret_cast<half*>(dsm + STAGE_BYTES + A_STAGE_BYTES) };

    wmma::fragment<wmma::accumulator, 16, 16, 16, float> acc[4][4];
    #pragma unroll
    for (int mi = 0; mi < 4; mi++)
        #pragma unroll
        for (int ni = 0; ni < 4; ni++) wmma::fill_fragment(acc[mi][ni], 0.0f);

    auto fill = [&](int s, int chunk) {
        const int tap = chunk >> 2;
        const int ic0 = (chunk & 3) * KCHUNK;
        const int dh  = tap / 3;
        const int dw  = tap - dh * 3;
        // A: 2 x 16B
        const __half* srcA = &g_wA[(((size_t)lab * LEGO_ + am) * NTAPS + tap) * CIN
                                   + ic0 + ah * 16];
        uint32_t dA = stA[s] + (am * LDA_K + ah * 16) * 2;
        cp16(dA,     srcA,     16);
        cp16(dA + 16, srcA + 8, 16);
        // B: 4 x 16B, row bk, segments bs0..bs0+3 (8 halfs each)
        #pragma unroll
        for (int j = 0; j < 4; j++) {
            const int n0  = (bs0 + j) * 8;             // pixel offset 0..255
            const int gr  = tile * 8 + (n0 >> 5) + dh - 1;
            const int ok  = ((unsigned)gr < 32u) ? 16 : 0;
            const __half* srcB = &g_xsh[dw][b][ic0 + bk][gr & 31][n0 & 31];
            cp16(stB[s] + (bk * LDB_N + n0) * 2, srcB, ok);
        }
        CP_COMMIT();
    };

    fill(0, 0);

    for (int chunk = 0; chunk < NCHUNKS; chunk++) {
        const int s = chunk & 1;
        CP_WAIT0();
        __syncthreads();     // stage s visible to all; prev reads of s^1 done
        if (chunk + 1 < NCHUNKS) fill(s ^ 1, chunk + 1);

        #pragma unroll
        for (int ks = 0; ks < 2; ks++) {
            wmma::fragment<wmma::matrix_a, 16, 16, 16, half,
                           wmma::row_major> af[4];
            #pragma unroll
            for (int mi = 0; mi < 4; mi++)
                wmma::load_matrix_sync(af[mi],
                    stAp[s] + (mrow + mi * 16) * LDA_K + ks * 16, LDA_K);
            #pragma unroll
            for (int ni = 0; ni < 4; ni++) {
                wmma::fragment<wmma::matrix_b, 16, 16, 16, half,
                               wmma::row_major> bf;
                wmma::load_matrix_sync(bf,
                    stBp[s] + (ks * 16) * LDB_N + ncol + ni * 16, LDB_N);
                #pragma unroll
                for (int mi = 0; mi < 4; mi++)
                    wmma::mma_sync(acc[mi][ni], af[mi], bf, acc[mi][ni]);
            }
        }
        __syncthreads();     // reads of stage s done before next fill hits it
    }

    // ---- feat staging (reuse stage smem) ----
    float* feat = reinterpret_cast<float*>(dsm);
    #pragma unroll
    for (int mi = 0; mi < 4; mi++)
        #pragma unroll
        for (int ni = 0; ni < 4; ni++)
            wmma::store_matrix_sync(
                feat + (mrow + mi * 16) * LDF + ncol + ni * 16,
                acc[mi][ni], LDF, wmma::mem_row_major);
    __syncthreads();

    // ---- coalesced scatter: 256 px per output channel ----
    float* outb = out + (size_t)b * OUTC * HW + pix0;
    for (int o = wid; o < OUTC; o += 8) {
        const int   sl = g_sel[o];
        const float sc = g_scale[o];
        #pragma unroll
        for (int h = 0; h < 2; h++) {
            float4 v = *reinterpret_cast<const float4*>(
                &feat[sl * LDF + h * 128 + lid * 4]);
            v.x *= sc; v.y *= sc; v.z *= sc; v.w *= sc;
            *reinterpret_cast<float4*>(
                outb + (size_t)o * HW + h * 128 + lid * 4) = v;
        }
    }
}

// ---------------------------------------------------------------------------
extern "C" void kernel_launch(void* const* d_in, const int* in_sizes, int n_in,
                              void* d_out, int out_size) {
    const float* x     = (const float*)d_in[0];
    const int*   label = (const int*)  d_in[1];
    const float* ff    = (const float*)d_in[2];
    const float* coeff = (const float*)d_in[3];
    const float* comb  = (const float*)d_in[4];
    float*       out   = (float*)d_out;

    static bool attr_set = false;
    if (!attr_set) {
        cudaFuncSetAttribute(conv_wmma_kernel,
                             cudaFuncAttributeMaxDynamicSharedMemorySize,
                             DSM_BYTES);
        attr_set = true;
    }

    select_kernel<<<1, OUTC>>>(coeff, comb);
    prep_w_kernel<<<(NLAB * LEGO_ * NTAPS * CIN + 255) / 256, 256>>>(ff);
    prep_x_kernel<<<(B_ * CIN * W_IMG + 255) / 256, 256>>>(x);

    dim3 grid(HW / NTILE, B_);   // (4, 128)
    conv_wmma_kernel<<<grid, 256, DSM_BYTES>>>(label, out);
}

// round 12
// speedup vs baseline: 3.5426x; 1.0270x over previous
#include <cuda_runtime.h>
#include <cuda_fp16.h>
#include <mma.h>
#include <cstdint>

using namespace nvcuda;

// Problem constants
#define B_      128
#define CIN     128
#define LEGO_   128
#define OUTC    512
#define HW      1024
#define W_IMG   32
#define NLAB    10
#define NTAPS   9
#define KCHUNK  32
#define NCHUNKS 36            // 9 taps * 4 ic-blocks  (k = tap*128 + ic)
#define NTILE   256           // pixels per CTA (8 image rows)
#define NSTAGE  3
#define LDA_K   40            // A smem ld (halfs): 80B rows
#define LDB_N   264           // B smem ld (halfs): 528B rows
#define LDF     260           // feat smem ld (floats)

#define A_STAGE_BYTES (128 * LDA_K * 2)     // 10240
#define B_STAGE_BYTES (KCHUNK * LDB_N * 2)  // 16896
#define STAGE_BYTES   (A_STAGE_BYTES + B_STAGE_BYTES)     // 27136
#define DSM_BYTES     (128 * LDF * 4)       // 133120 (>= 3*STAGE_BYTES=81408)

__device__ int   g_sel[OUTC];
__device__ float g_scale[OUTC];
__device__ __align__(16) __half g_wA[NLAB * LEGO_ * NTAPS * CIN];  // [lab][m][tap][ic]
__device__ __align__(16) __half g_xsh[3][B_][CIN][W_IMG][W_IMG];   // [dw][b][ic][r][c]

__device__ __forceinline__ uint32_t smem_u32(const void* p) {
    uint32_t a;
    asm("{ .reg .u64 t; cvta.to.shared.u64 t, %1; cvt.u32.u64 %0, t; }"
        : "=r"(a) : "l"(p));
    return a;
}
__device__ __forceinline__ void cp16(uint32_t dst, const void* src, int srcsize) {
    asm volatile("cp.async.cg.shared.global [%0], [%1], 16, %2;"
                 :: "r"(dst), "l"(__cvta_generic_to_global(src)), "r"(srcsize)
                 : "memory");
}
#define CP_COMMIT() asm volatile("cp.async.commit_group;" ::: "memory")
#define CP_WAIT1()  asm volatile("cp.async.wait_group 1;" ::: "memory")

// ---------------------------------------------------------------------------
// Kernel 1: forward select map.
// ---------------------------------------------------------------------------
__global__ void select_kernel(const float* __restrict__ coeff,
                              const float* __restrict__ comb) {
    int o = threadIdx.x;
    const float* row = comb + o * LEGO_;
    float m = row[0];
    int mi = 0;
    #pragma unroll 4
    for (int l = 1; l < LEGO_; l++) {
        float v = row[l];
        if (v > m) { m = v; mi = l; }
    }
    g_sel[o]   = mi;
    g_scale[o] = coeff[o * LEGO_ + mi];
}

// ---------------------------------------------------------------------------
// Kernel 2: weight transpose+convert: wA[lab][m][tap][ic] = ff[lab][m][ic][tap]
// ---------------------------------------------------------------------------
__global__ void prep_w_kernel(const float* __restrict__ ff) {
    int idx = blockIdx.x * 256 + threadIdx.x;
    if (idx >= NLAB * LEGO_ * NTAPS * CIN) return;
    int ic  = idx & 127;
    int tap = (idx >> 7) % NTAPS;
    int m   = (idx / (NTAPS * CIN)) & 127;
    int lab = idx / (LEGO_ * NTAPS * CIN);
    float v = ff[((size_t)(lab * LEGO_ + m) * CIN + ic) * NTAPS + tap];
    g_wA[idx] = __float2half_rn(v);
}

// ---------------------------------------------------------------------------
// Kernel 3: 3 column-shifted fp16 copies of x: xsh[dw][b][ic][r][c] =
// x[b][ic][r][c+dw-1] (0 outside).
// ---------------------------------------------------------------------------
__global__ void prep_x_kernel(const float* __restrict__ x) {
    int idx = blockIdx.x * 256 + threadIdx.x;       // over 128*128*32
    if (idx >= B_ * CIN * W_IMG) return;
    const float* src = x + (size_t)idx * W_IMG;
    float v[32];
    #pragma unroll
    for (int j = 0; j < 8; j++) {
        float4 f = *reinterpret_cast<const float4*>(src + j * 4);
        v[j * 4] = f.x; v[j * 4 + 1] = f.y; v[j * 4 + 2] = f.z; v[j * 4 + 3] = f.w;
    }
    #pragma unroll
    for (int dw = 0; dw < 3; dw++) {
        __half h[32];
        #pragma unroll
        for (int c = 0; c < 32; c++) {
            int s = c + dw - 1;
            h[c] = __float2half_rn((s >= 0 && s < 32) ? v[s] : 0.0f);
        }
        uint4* dst = reinterpret_cast<uint4*>(
            &g_xsh[dw][0][0][0][0] + (size_t)idx * W_IMG);
        #pragma unroll
        for (int j = 0; j < 4; j++)
            dst[j] = reinterpret_cast<const uint4*>(h)[j];
    }
}

// ---------------------------------------------------------------------------
// Kernel 4: fp16 wmma GEMM conv, 16 warps (32x64 warp tiles), 3-stage
// cp.async ring (wait_group 1), fused scatter.
// grid = (4 tiles, 128 batches), 512 threads.
// ---------------------------------------------------------------------------
__global__ __launch_bounds__(512, 1)
void conv_wmma_kernel(const int* __restrict__ label,
                      float*     __restrict__ out) {
    extern __shared__ char dsm[];

    const int tid  = threadIdx.x;
    const int wid  = tid >> 5;       // 0..15
    const int lid  = tid & 31;
    const int tile = blockIdx.x;     // 0..3
    const int b    = blockIdx.y;     // 0..127
    const int pix0 = tile * NTILE;
    const int lab  = label[b];

    // fill roles (512 threads)
    const int am  = tid >> 2, ah = tid & 3;   // A: row m, 8-half seg -> 1 cp16
    const int bk  = tid >> 4;                 // B: k-row within chunk (0..31)
    const int bs0 = (tid & 15) * 2;           // B: first 8-half seg (of 32) -> 2 cp16

    // warp tile: 32 M x 64 N (warps: 4 in M x 4 in N)
    const int mrow = (wid & 3) * 32;
    const int ncol = (wid >> 2) * 64;

    uint32_t stA[NSTAGE]; half* stAp[NSTAGE]; half* stBp[NSTAGE];
    #pragma unroll
    for (int s = 0; s < NSTAGE; s++) {
        stA[s]  = smem_u32(dsm + s * STAGE_BYTES);
        stAp[s] = reinterpret_cast<half*>(dsm + s * STAGE_BYTES);
        stBp[s] = reinterpret_cast<half*>(dsm + s * STAGE_BYTES + A_STAGE_BYTES);
    }

    wmma::fragment<wmma::accumulator, 16, 16, 16, float> acc[2][4];
    #pragma unroll
    for (int mi = 0; mi < 2; mi++)
        #pragma unroll
        for (int ni = 0; ni < 4; ni++) wmma::fill_fragment(acc[mi][ni], 0.0f);

    auto fill = [&](int s, int chunk) {
        const int tap = chunk >> 2;
        const int ic0 = (chunk & 3) * KCHUNK;
        const int dh  = tap / 3;
        const int dw  = tap - dh * 3;
        // A: one 16B seg per thread
        const __half* srcA = &g_wA[(((size_t)lab * LEGO_ + am) * NTAPS + tap) * CIN
                                   + ic0 + ah * 8];
        cp16(stA[s] + (am * LDA_K + ah * 8) * 2, srcA, 16);
        // B: two 16B segs per thread, row bk
        #pragma unroll
        for (int j = 0; j < 2; j++) {
            const int n0 = (bs0 + j) * 8;              // pixel offset 0..255
            const int gr = tile * 8 + (n0 >> 5) + dh - 1;
            const int ok = ((unsigned)gr < 32u) ? 16 : 0;
            const __half* srcB = &g_xsh[dw][b][ic0 + bk][gr & 31][n0 & 31];
            cp16(stA[s] + A_STAGE_BYTES + (bk * LDB_N + n0) * 2, srcB, ok);
        }
    };

    // prologue: 2 fills in flight
    fill(0, 0); CP_COMMIT();
    fill(1, 1); CP_COMMIT();

    for (int chunk = 0; chunk < NCHUNKS; chunk++) {
        const int s = chunk % NSTAGE;
        CP_WAIT1();          // fill(chunk) complete (one younger group may fly)
        __syncthreads();     // stage s visible; compute(chunk-1) done in all warps
        if (chunk + 2 < NCHUNKS) fill((chunk + 2) % NSTAGE, chunk + 2);
        CP_COMMIT();         // empty group near the tail keeps accounting fixed

        #pragma unroll
        for (int ks = 0; ks < 2; ks++) {
            wmma::fragment<wmma::matrix_a, 16, 16, 16, half,
                           wmma::row_major> af[2];
            #pragma unroll
            for (int mi = 0; mi < 2; mi++)
                wmma::load_matrix_sync(af[mi],
                    stAp[s] + (mrow + mi * 16) * LDA_K + ks * 16, LDA_K);
            #pragma unroll
            for (int ni = 0; ni < 4; ni++) {
                wmma::fragment<wmma::matrix_b, 16, 16, 16, half,
                               wmma::row_major> bf;
                wmma::load_matrix_sync(bf,
                    stBp[s] + (ks * 16) * LDB_N + ncol + ni * 16, LDB_N);
                #pragma unroll
                for (int mi = 0; mi < 2; mi++)
                    wmma::mma_sync(acc[mi][ni], af[mi], bf, acc[mi][ni]);
            }
        }
    }

    __syncthreads();         // all compute done before overlaying feat
    float* feat = reinterpret_cast<float*>(dsm);
    #pragma unroll
    for (int mi = 0; mi < 2; mi++)
        #pragma unroll
        for (int ni = 0; ni < 4; ni++)
            wmma::store_matrix_sync(
                feat + (mrow + mi * 16) * LDF + ncol + ni * 16,
                acc[mi][ni], LDF, wmma::mem_row_major);
    __syncthreads();

    // ---- coalesced scatter: 256 px per output channel ----
    float* outb = out + (size_t)b * OUTC * HW + pix0;
    for (int o = wid; o < OUTC; o += 16) {
        const int   sl = g_sel[o];
        const float sc = g_scale[o];
        #pragma unroll
        for (int h = 0; h < 2; h++) {
            float4 v = *reinterpret_cast<const float4*>(
                &feat[sl * LDF + h * 128 + lid * 4]);
            v.x *= sc; v.y *= sc; v.z *= sc; v.w *= sc;
            *reinterpret_cast<float4*>(
                outb + (size_t)o * HW + h * 128 + lid * 4) = v;
        }
    }
}

// ---------------------------------------------------------------------------
extern "C" void kernel_launch(void* const* d_in, const int* in_sizes, int n_in,
                              void* d_out, int out_size) {
    const float* x     = (const float*)d_in[0];
    const int*   label = (const int*)  d_in[1];
    const float* ff    = (const float*)d_in[2];
    const float* coeff = (const float*)d_in[3];
    const float* comb  = (const float*)d_in[4];
    float*       out   = (float*)d_out;

    static bool attr_set = false;
    if (!attr_set) {
        cudaFuncSetAttribute(conv_wmma_kernel,
                             cudaFuncAttributeMaxDynamicSharedMemorySize,
                             DSM_BYTES);
        attr_set = true;
    }

    select_kernel<<<1, OUTC>>>(coeff, comb);
    prep_w_kernel<<<(NLAB * LEGO_ * NTAPS * CIN + 255) / 256, 256>>>(ff);
    prep_x_kernel<<<(B_ * CIN * W_IMG + 255) / 256, 256>>>(x);

    dim3 grid(HW / NTILE, B_);   // (4, 128)
    conv_wmma_kernel<<<grid, 512, DSM_BYTES>>>(label, out);
}

// round 13
// speedup vs baseline: 3.7750x; 1.0656x over previous
#include <cuda_runtime.h>
#include <cuda_fp16.h>
#include <mma.h>
#include <cstdint>

using namespace nvcuda;

// Problem constants
#define B_      128
#define CIN     128
#define LEGO_   128
#define OUTC    512
#define HW      1024
#define W_IMG   32
#define NLAB    10
#define NTAPS   9
#define KCHUNK  64
#define NCHUNKS 18            // 9 taps * 2 ic-blocks  (k = tap*128 + ic)
#define NTILE   256           // pixels per CTA (8 image rows)
#define NSTAGE  2
#define LDA_K   72            // A smem ld (halfs): 144B rows (64 + 8 pad)
#define LDB_N   264           // B smem ld (halfs): 528B rows
#define LDF     260           // feat smem ld (floats)

#define A_STAGE_BYTES (128 * LDA_K * 2)     // 18432
#define B_STAGE_BYTES (KCHUNK * LDB_N * 2)  // 33792
#define STAGE_BYTES   (A_STAGE_BYTES + B_STAGE_BYTES)   // 52224
#define DSM_BYTES     (128 * LDF * 4)       // 133120 (>= 2*STAGE_BYTES=104448)

__device__ int   g_sel[OUTC];
__device__ float g_scale[OUTC];
__device__ __align__(16) __half g_wA[NLAB * LEGO_ * NTAPS * CIN];  // [lab][m][tap][ic]
__device__ __align__(16) __half g_xsh[3][B_][CIN][W_IMG][W_IMG];   // [dw][b][ic][r][c]

__device__ __forceinline__ uint32_t smem_u32(const void* p) {
    uint32_t a;
    asm("{ .reg .u64 t; cvta.to.shared.u64 t, %1; cvt.u32.u64 %0, t; }"
        : "=r"(a) : "l"(p));
    return a;
}
__device__ __forceinline__ void cp16(uint32_t dst, const void* src, int srcsize) {
    asm volatile("cp.async.cg.shared.global [%0], [%1], 16, %2;"
                 :: "r"(dst), "l"(__cvta_generic_to_global(src)), "r"(srcsize)
                 : "memory");
}
#define CP_COMMIT() asm volatile("cp.async.commit_group;" ::: "memory")
#define CP_WAIT0()  asm volatile("cp.async.wait_group 0;" ::: "memory")

// ---------------------------------------------------------------------------
// Kernel 1: forward select map, warp-per-o.
// grid = 32 blocks x 512 threads (16 warps) -> 512 output channels.
// argmax semantics: first occurrence of the max (strict >).
// ---------------------------------------------------------------------------
__global__ void select_kernel(const float* __restrict__ coeff,
                              const float* __restrict__ comb) {
    const int wid = threadIdx.x >> 5;
    const int lid = threadIdx.x & 31;
    const int o   = blockIdx.x * 16 + wid;

    const float* row = comb + o * LEGO_;
    // lane handles l = lid*4 .. lid*4+3 (increasing l within and across lanes)
    float4 v = *reinterpret_cast<const float4*>(row + lid * 4);
    float m  = v.x; int mi = lid * 4;
    if (v.y > m) { m = v.y; mi = lid * 4 + 1; }
    if (v.z > m) { m = v.z; mi = lid * 4 + 2; }
    if (v.w > m) { m = v.w; mi = lid * 4 + 3; }
    // warp reduce: prefer larger m; on tie, smaller index (first occurrence)
    #pragma unroll
    for (int off = 16; off > 0; off >>= 1) {
        float m2 = __shfl_down_sync(0xFFFFFFFF, m, off);
        int  mi2 = __shfl_down_sync(0xFFFFFFFF, mi, off);
        if (m2 > m || (m2 == m && mi2 < mi)) { m = m2; mi = mi2; }
    }
    if (lid == 0) {
        g_sel[o]   = mi;
        g_scale[o] = coeff[o * LEGO_ + mi];
    }
}

// ---------------------------------------------------------------------------
// Kernel 2: weight transpose+convert via smem.
// block per (lab, m): wA[lab][m][tap][ic] = ff[lab][m][ic][tap]
// ---------------------------------------------------------------------------
__global__ void prep_w_kernel(const float* __restrict__ ff) {
    __shared__ float s[NTAPS * CIN];         // 1152
    const int bm  = blockIdx.x;              // 0..1279  (lab*128 + m)
    const int t   = threadIdx.x;             // 0..127
    const float* src = ff + (size_t)bm * NTAPS * CIN;
    #pragma unroll
    for (int j = 0; j < 9; j++) s[t + j * 128] = src[t + j * 128];
    __syncthreads();
    __half* dst = g_wA + (size_t)bm * NTAPS * CIN;
    #pragma unroll
    for (int j = 0; j < 9; j++) {
        int e   = t + j * 128;               // = tap*128 + ic
        int tap = e >> 7, ic = e & 127;
        dst[e] = __float2half_rn(s[ic * 9 + tap]);   // stride-9: bank-clean
    }
}

// ---------------------------------------------------------------------------
// Kernel 3: 3 column-shifted fp16 copies of x: xsh[dw][b][ic][r][c] =
// x[b][ic][r][c+dw-1] (0 outside).
// ---------------------------------------------------------------------------
__global__ void prep_x_kernel(const float* __restrict__ x) {
    int idx = blockIdx.x * 256 + threadIdx.x;       // over 128*128*32
    if (idx >= B_ * CIN * W_IMG) return;
    const float* src = x + (size_t)idx * W_IMG;
    float v[32];
    #pragma unroll
    for (int j = 0; j < 8; j++) {
        float4 f = *reinterpret_cast<const float4*>(src + j * 4);
        v[j * 4] = f.x; v[j * 4 + 1] = f.y; v[j * 4 + 2] = f.z; v[j * 4 + 3] = f.w;
    }
    #pragma unroll
    for (int dw = 0; dw < 3; dw++) {
        __half h[32];
        #pragma unroll
        for (int c = 0; c < 32; c++) {
            int s = c + dw - 1;
            h[c] = __float2half_rn((s >= 0 && s < 32) ? v[s] : 0.0f);
        }
        uint4* dst = reinterpret_cast<uint4*>(
            &g_xsh[dw][0][0][0][0] + (size_t)idx * W_IMG);
        #pragma unroll
        for (int j = 0; j < 4; j++)
            dst[j] = reinterpret_cast<const uint4*>(h)[j];
    }
}

// ---------------------------------------------------------------------------
// Kernel 4: fp16 wmma GEMM conv, 16 warps (32x64 warp tiles), KCHUNK=64,
// 2-stage cp.async pipeline (one barrier per chunk), fused scatter.
// grid = (4 tiles, 128 batches), 512 threads.
// ---------------------------------------------------------------------------
__global__ __launch_bounds__(512, 1)
void conv_wmma_kernel(const int* __restrict__ label,
                      float*     __restrict__ out) {
    extern __shared__ char dsm[];

    const int tid  = threadIdx.x;
    const int wid  = tid >> 5;       // 0..15
    const int lid  = tid & 31;
    const int tile = blockIdx.x;     // 0..3
    const int b    = blockIdx.y;     // 0..127
    const int pix0 = tile * NTILE;
    const int lab  = label[b];

    // fill roles (512 threads)
    const int am  = tid >> 2, ah = tid & 3;   // A: row m, 16-half seg (2 cp16)
    const int bk  = tid >> 3;                 // B: k-row within chunk (0..63)
    const int bs0 = (tid & 7) * 4;            // B: first 8-half seg (of 32) -> 4 cp16

    // warp tile: 32 M x 64 N (warps: 4 in M x 4 in N)
    const int mrow = (wid & 3) * 32;
    const int ncol = (wid >> 2) * 64;

    uint32_t stA[NSTAGE]; half* stAp[NSTAGE]; half* stBp[NSTAGE];
    #pragma unroll
    for (int s = 0; s < NSTAGE; s++) {
        stA[s]  = smem_u32(dsm + s * STAGE_BYTES);
        stAp[s] = reinterpret_cast<half*>(dsm + s * STAGE_BYTES);
        stBp[s] = reinterpret_cast<half*>(dsm + s * STAGE_BYTES + A_STAGE_BYTES);
    }

    wmma::fragment<wmma::accumulator, 16, 16, 16, float> acc[2][4];
    #pragma unroll
    for (int mi = 0; mi < 2; mi++)
        #pragma unroll
        for (int ni = 0; ni < 4; ni++) wmma::fill_fragment(acc[mi][ni], 0.0f);

    auto fill = [&](int s, int chunk) {
        const int tap = chunk >> 1;             // 0..8
        const int ic0 = (chunk & 1) * KCHUNK;   // 0 or 64
        const int dh  = tap / 3;
        const int dw  = tap - dh * 3;
        // A: 16 halfs per thread (2 cp16)
        const __half* srcA = &g_wA[(((size_t)lab * LEGO_ + am) * NTAPS + tap) * CIN
                                   + ic0 + ah * 16];
        uint32_t dA = stA[s] + (am * LDA_K + ah * 16) * 2;
        cp16(dA,      srcA,     16);
        cp16(dA + 16, srcA + 8, 16);
        // B: 4 x 16B segs, row bk
        #pragma unroll
        for (int j = 0; j < 4; j++) {
            const int n0 = (bs0 + j) * 8;              // pixel offset 0..255
            const int gr = tile * 8 + (n0 >> 5) + dh - 1;
            const int ok = ((unsigned)gr < 32u) ? 16 : 0;
            const __half* srcB = &g_xsh[dw][b][ic0 + bk][gr & 31][n0 & 31];
            cp16(stA[s] + A_STAGE_BYTES + (bk * LDB_N + n0) * 2, srcB, ok);
        }
        CP_COMMIT();
    };

    fill(0, 0);

    for (int chunk = 0; chunk < NCHUNKS; chunk++) {
        const int s = chunk & 1;
        CP_WAIT0();          // fill(chunk) landed
        __syncthreads();     // stage s visible; compute(chunk-1) reads of s^1 done
        if (chunk + 1 < NCHUNKS) fill(s ^ 1, chunk + 1);

        #pragma unroll
        for (int ks = 0; ks < 4; ks++) {
            wmma::fragment<wmma::matrix_a, 16, 16, 16, half,
                           wmma::row_major> af[2];
            #pragma unroll
            for (int mi = 0; mi < 2; mi++)
                wmma::load_matrix_sync(af[mi],
                    stAp[s] + (mrow + mi * 16) * LDA_K + ks * 16, LDA_K);
            #pragma unroll
            for (int ni = 0; ni < 4; ni++) {
                wmma::fragment<wmma::matrix_b, 16, 16, 16, half,
                               wmma::row_major> bf;
                wmma::load_matrix_sync(bf,
                    stBp[s] + (ks * 16) * LDB_N + ncol + ni * 16, LDB_N);
                #pragma unroll
                for (int mi = 0; mi < 2; mi++)
                    wmma::mma_sync(acc[mi][ni], af[mi], bf, acc[mi][ni]);
            }
        }
    }

    __syncthreads();         // all compute done before overlaying feat
    float* feat = reinterpret_cast<float*>(dsm);
    #pragma unroll
    for (int mi = 0; mi < 2; mi++)
        #pragma unroll
        for (int ni = 0; ni < 4; ni++)
            wmma::store_matrix_sync(
                feat + (mrow + mi * 16) * LDF + ncol + ni * 16,
                acc[mi][ni], LDF, wmma::mem_row_major);
    __syncthreads();

    // ---- coalesced scatter: 256 px per output channel ----
    float* outb = out + (size_t)b * OUTC * HW + pix0;
    for (int o = wid; o < OUTC; o += 16) {
        const int   sl = g_sel[o];
        const float sc = g_scale[o];
        #pragma unroll
        for (int h = 0; h < 2; h++) {
            float4 v = *reinterpret_cast<const float4*>(
                &feat[sl * LDF + h * 128 + lid * 4]);
            v.x *= sc; v.y *= sc; v.z *= sc; v.w *= sc;
            *reinterpret_cast<float4*>(
                outb + (size_t)o * HW + h * 128 + lid * 4) = v;
        }
    }
}

// ---------------------------------------------------------------------------
extern "C" void kernel_launch(void* const* d_in, const int* in_sizes, int n_in,
                              void* d_out, int out_size) {
    const float* x     = (const float*)d_in[0];
    const int*   label = (const int*)  d_in[1];
    const float* ff    = (const float*)d_in[2];
    const float* coeff = (const float*)d_in[3];
    const float* comb  = (const float*)d_in[4];
    float*       out   = (float*)d_out;

    static bool attr_set = false;
    if (!attr_set) {
        cudaFuncSetAttribute(conv_wmma_kernel,
                             cudaFuncAttributeMaxDynamicSharedMemorySize,
                             DSM_BYTES);
        attr_set = true;
    }

    select_kernel<<<32, 512>>>(coeff, comb);
    prep_w_kernel<<<NLAB * LEGO_, 128>>>(ff);
    prep_x_kernel<<<(B_ * CIN * W_IMG + 255) / 256, 256>>>(x);

    dim3 grid(HW / NTILE, B_);   // (4, 128)
    conv_wmma_kernel<<<grid, 512, DSM_BYTES>>>(label, out);
}

// round 16
// speedup vs baseline: 4.0292x; 1.0673x over previous
#include <cuda_runtime.h>
#include <cuda_fp16.h>
#include <mma.h>
#include <cstdint>

using namespace nvcuda;

// Problem constants
#define B_      128
#define CIN     128
#define LEGO_   128
#define OUTC    512
#define HW      1024
#define W_IMG   32
#define NLAB    10
#define NTAPS   9
#define KCHUNK  64
#define NCHUNKS 18            // 9 taps * 2 ic-blocks  (k = tap*128 + ic)
#define NTILE   128           // pixels per CTA (4 image rows)
#define NSTAGE  2
#define LDA_K   72            // A smem ld (halfs): 144B rows (64 + 8 pad)
#define LDB_N   136           // B smem ld (halfs): 272B rows (128 + 8 pad)
#define LDF     132           // feat smem ld (floats)

#define A_STAGE_BYTES (128 * LDA_K * 2)     // 18432
#define B_STAGE_BYTES (KCHUNK * LDB_N * 2)  // 17408
#define STAGE_BYTES   (A_STAGE_BYTES + B_STAGE_BYTES)   // 35840
#define DSM_BYTES     (NSTAGE * STAGE_BYTES)            // 71680 (> feat 67584)

__device__ int   g_sel[OUTC];
__device__ float g_scale[OUTC];
__device__ __align__(16) __half g_wA[NLAB * LEGO_ * NTAPS * CIN];  // [lab][m][tap][ic]
__device__ __align__(16) __half g_xsh[3][B_][CIN][W_IMG][W_IMG];   // [dw][b][ic][r][c]

__device__ __forceinline__ uint32_t smem_u32(const void* p) {
    uint32_t a;
    asm("{ .reg .u64 t; cvta.to.shared.u64 t, %1; cvt.u32.u64 %0, t; }"
        : "=r"(a) : "l"(p));
    return a;
}
__device__ __forceinline__ void cp16(uint32_t dst, const void* src, int srcsize) {
    asm volatile("cp.async.cg.shared.global [%0], [%1], 16, %2;"
                 :: "r"(dst), "l"(__cvta_generic_to_global(src)), "r"(srcsize)
                 : "memory");
}
#define CP_COMMIT() asm volatile("cp.async.commit_group;" ::: "memory")
#define CP_WAIT0()  asm volatile("cp.async.wait_group 0;" ::: "memory")

// ---------------------------------------------------------------------------
// Kernel 1: forward select map, warp-per-o (argmax = first max, strict >).
// ---------------------------------------------------------------------------
__global__ void select_kernel(const float* __restrict__ coeff,
                              const float* __restrict__ comb) {
    const int wid = threadIdx.x >> 5;
    const int lid = threadIdx.x & 31;
    const int o   = blockIdx.x * 16 + wid;

    const float* row = comb + o * LEGO_;
    float4 v = *reinterpret_cast<const float4*>(row + lid * 4);
    float m  = v.x; int mi = lid * 4;
    if (v.y > m) { m = v.y; mi = lid * 4 + 1; }
    if (v.z > m) { m = v.z; mi = lid * 4 + 2; }
    if (v.w > m) { m = v.w; mi = lid * 4 + 3; }
    #pragma unroll
    for (int off = 16; off > 0; off >>= 1) {
        float m2 = __shfl_down_sync(0xFFFFFFFF, m, off);
        int  mi2 = __shfl_down_sync(0xFFFFFFFF, mi, off);
        if (m2 > m || (m2 == m && mi2 < mi)) { m = m2; mi = mi2; }
    }
    if (lid == 0) {
        g_sel[o]   = mi;
        g_scale[o] = coeff[o * LEGO_ + mi];
    }
}

// ---------------------------------------------------------------------------
// Kernel 2: weight transpose+convert via smem, block per (lab, m).
// ---------------------------------------------------------------------------
__global__ void prep_w_kernel(const float* __restrict__ ff) {
    __shared__ float s[NTAPS * CIN];         // 1152
    const int bm  = blockIdx.x;              // lab*128 + m
    const int t   = threadIdx.x;             // 0..127
    const float* src = ff + (size_t)bm * NTAPS * CIN;
    #pragma unroll
    for (int j = 0; j < 9; j++) s[t + j * 128] = src[t + j * 128];
    __syncthreads();
    __half* dst = g_wA + (size_t)bm * NTAPS * CIN;
    #pragma unroll
    for (int j = 0; j < 9; j++) {
        int e   = t + j * 128;               // = tap*128 + ic
        int tap = e >> 7, ic = e & 127;
        dst[e] = __float2half_rn(s[ic * 9 + tap]);
    }
}

// ---------------------------------------------------------------------------
// Kernel 3: 3 column-shifted fp16 copies of x.
// ---------------------------------------------------------------------------
__global__ void prep_x_kernel(const float* __restrict__ x) {
    int idx = blockIdx.x * 256 + threadIdx.x;       // over 128*128*32
    if (idx >= B_ * CIN * W_IMG) return;
    const float* src = x + (size_t)idx * W_IMG;
    float v[32];
    #pragma unroll
    for (int j = 0; j < 8; j++) {
        float4 f = *reinterpret_cast<const float4*>(src + j * 4);
        v[j * 4] = f.x; v[j * 4 + 1] = f.y; v[j * 4 + 2] = f.z; v[j * 4 + 3] = f.w;
    }
    #pragma unroll
    for (int dw = 0; dw < 3; dw++) {
        __half h[32];
        #pragma unroll
        for (int c = 0; c < 32; c++) {
            int s = c + dw - 1;
            h[c] = __float2half_rn((s >= 0 && s < 32) ? v[s] : 0.0f);
        }
        uint4* dst = reinterpret_cast<uint4*>(
            &g_xsh[dw][0][0][0][0] + (size_t)idx * W_IMG);
        #pragma unroll
        for (int j = 0; j < 4; j++)
            dst[j] = reinterpret_cast<const uint4*>(h)[j];
    }
}

// ---------------------------------------------------------------------------
// Kernel 4: fp16 wmma GEMM conv, 8 warps (32x64 tiles), KCHUNK=64, cp.async
// 2-stage, 2 CTAs/SM (independent barrier domains), fused scatter.
// grid = (8 tiles, 128 batches), 256 threads.
// ---------------------------------------------------------------------------
__global__ __launch_bounds__(256, 2)
void conv_wmma_kernel(const int* __restrict__ label,
                      float*     __restrict__ out) {
    extern __shared__ char dsm[];

    const int tid  = threadIdx.x;
    const int wid  = tid >> 5;       // 0..7
    const int lid  = tid & 31;
    const int tile = blockIdx.x;     // 0..7
    const int b    = blockIdx.y;     // 0..127
    const int pix0 = tile * NTILE;
    const int lab  = label[b];

    // fill roles (256 threads)
    const int am  = tid >> 1, ah = tid & 1;   // A: row m, 32-half half (4 cp16)
    const int bk  = tid >> 2;                 // B: k-row (0..63)
    const int bs  = tid & 3;                  // B: 32-half seg = image row (4 cp16)

    // warp tile: 32 M x 64 N (warps: 4 in M x 2 in N)
    const int mrow = (wid & 3) * 32;
    const int ncol = (wid >> 2) * 64;

    uint32_t stA[NSTAGE]; half* stAp[NSTAGE]; half* stBp[NSTAGE];
    #pragma unroll
    for (int s = 0; s < NSTAGE; s++) {
        stA[s]  = smem_u32(dsm + s * STAGE_BYTES);
        stAp[s] = reinterpret_cast<half*>(dsm + s * STAGE_BYTES);
        stBp[s] = reinterpret_cast<half*>(dsm + s * STAGE_BYTES + A_STAGE_BYTES);
    }

    wmma::fragment<wmma::accumulator, 16, 16, 16, float> acc[2][4];
    #pragma unroll
    for (int mi = 0; mi < 2; mi++)
        #pragma unroll
        for (int ni = 0; ni < 4; ni++) wmma::fill_fragment(acc[mi][ni], 0.0f);

    auto fill = [&](int s, int chunk) {
        const int tap = chunk >> 1;             // 0..8
        const int ic0 = (chunk & 1) * KCHUNK;   // 0 or 64
        const int dh  = tap / 3;
        const int dw  = tap - dh * 3;
        // A: 32 halfs per thread (4 cp16)
        const __half* srcA = &g_wA[(((size_t)lab * LEGO_ + am) * NTAPS + tap) * CIN
                                   + ic0 + ah * 32];
        uint32_t dA = stA[s] + (am * LDA_K + ah * 32) * 2;
        #pragma unroll
        for (int j = 0; j < 4; j++)
            cp16(dA + j * 16, srcA + j * 8, 16);
        // B: one image row (32 px) for k-row bk: 4 cp16
        const int gr = tile * 4 + bs + dh - 1;
        const int ok = ((unsigned)gr < 32u) ? 16 : 0;
        const __half* srcB = &g_xsh[dw][b][ic0 + bk][gr & 31][0];
        uint32_t dB = stA[s] + A_STAGE_BYTES + (bk * LDB_N + bs * 32) * 2;
        #pragma unroll
        for (int j = 0; j < 4; j++)
            cp16(dB + j * 16, srcB + j * 8, ok);
        CP_COMMIT();
    };

    fill(0, 0);

    for (int chunk = 0; chunk < NCHUNKS; chunk++) {
        const int s = chunk & 1;
        CP_WAIT0();          // fill(chunk) landed
        __syncthreads();     // stage visible; prior reads of s^1 done
        if (chunk + 1 < NCHUNKS) fill(s ^ 1, chunk + 1);

        #pragma unroll
        for (int ks = 0; ks < 4; ks++) {
            wmma::fragment<wmma::matrix_a, 16, 16, 16, half,
                           wmma::row_major> af[2];
            #pragma unroll
            for (int mi = 0; mi < 2; mi++)
                wmma::load_matrix_sync(af[mi],
                    stAp[s] + (mrow + mi * 16) * LDA_K + ks * 16, LDA_K);
            #pragma unroll
            for (int ni = 0; ni < 4; ni++) {
                wmma::fragment<wmma::matrix_b, 16, 16, 16, half,
                               wmma::row_major> bf;
                wmma::load_matrix_sync(bf,
                    stBp[s] + (ks * 16) * LDB_N + ncol + ni * 16, LDB_N);
                #pragma unroll
                for (int mi = 0; mi < 2; mi++)
                    wmma::mma_sync(acc[mi][ni], af[mi], bf, acc[mi][ni]);
            }
        }
    }

    __syncthreads();         // all compute done before overlaying feat
    float* feat = reinterpret_cast<float*>(dsm);
    #pragma unroll
    for (int mi = 0; mi < 2; mi++)
        #pragma unroll
        for (int ni = 0; ni < 4; ni++)
            wmma::store_matrix_sync(
                feat + (mrow + mi * 16) * LDF + ncol + ni * 16,
                acc[mi][ni], LDF, wmma::mem_row_major);
    __syncthreads();

    // ---- coalesced scatter: 128 px per output channel, float4 per lane ----
    float* outb = out + (size_t)b * OUTC * HW + pix0;
    for (int o = wid; o < OUTC; o += 8) {
        const int   sl = g_sel[o];
        const float sc = g_scale[o];
        float4 v = *reinterpret_cast<const float4*>(&feat[sl * LDF + lid * 4]);
        v.x *= sc; v.y *= sc; v.z *= sc; v.w *= sc;
        *reinterpret_cast<float4*>(outb + (size_t)o * HW + lid * 4) = v;
    }
}

// ---------------------------------------------------------------------------
extern "C" void kernel_launch(void* const* d_in, const int* in_sizes, int n_in,
                              void* d_out, int out_size) {
    const float* x     = (const float*)d_in[0];
    const int*   label = (const int*)  d_in[1];
    const float* ff    = (const float*)d_in[2];
    const float* coeff = (const float*)d_in[3];
    const float* comb  = (const float*)d_in[4];
    float*       out   = (float*)d_out;

    static bool attr_set = false;
    if (!attr_set) {
        cudaFuncSetAttribute(conv_wmma_kernel,
                             cudaFuncAttributeMaxDynamicSharedMemorySize,
                             DSM_BYTES);
        attr_set = true;
    }

    select_kernel<<<32, 512>>>(coeff, comb);
    prep_w_kernel<<<NLAB * LEGO_, 128>>>(ff);
    prep_x_kernel<<<(B_ * CIN * W_IMG + 255) / 256, 256>>>(x);

    dim3 grid(HW / NTILE, B_);   // (8, 128)
    conv_wmma_kernel<<<grid, 256, DSM_BYTES>>>(label, out);
}